// round 3
// baseline (speedup 1.0000x reference)
#include <cuda_runtime.h>
#include <cuda_bf16.h>

// WeightedBiasEncoder: out[B*H, N+1, N+1]
//   out[bh][0][*] = token[h];  out[bh][r][0] = token[h] (r>=1)
//   out[bh][r][c] = emb[spatial[(b*N + r-1)*N + (c-1)]][h]   (r,c >= 1)
//
// H==8 fast path: emb row = 2 float4s; per spatial index 1 LDG + 2 LDS.128
// serve all 8 head planes. This round: 2 rows per block with 8 front-batched
// LDGs per thread (MLP), and a 4x bank-shifted smem replica of the emb table
// (copy stride 266 float4 == 32B mod 128B -> lane&3 picks a disjoint bank
// quarter) to cut LDS.128 gather conflicts.

#define TPB 128
#define CPY 266   // float4 stride between table copies (266 % 8 == 2 -> 32B bank shift)

__global__ __launch_bounds__(TPB) void wbe_fast8(
    const int*   __restrict__ spatial,   // [B*N*N]
    const float* __restrict__ emb,       // [SP1, 8]
    const float* __restrict__ token,     // [8]
    float*       __restrict__ out,       // [B*8, N+1, N+1]
    int N, int SP1)
{
    __shared__ float4 emb4s[4 * CPY];    // 4 replicas, supports SP1 <= 133
    const int tid = threadIdx.x;
    const int n4  = SP1 * 2;
    const float4* __restrict__ emb4g = (const float4*)emb;
    for (int i = tid; i < n4; i += TPB) {
        float4 v = emb4g[i];
        emb4s[i] = v;
        emb4s[CPY + i] = v;
        emb4s[2 * CPY + i] = v;
        emb4s[3 * CPY + i] = v;
    }
    __syncthreads();

    const int bx = blockIdx.x;
    const int b  = blockIdx.y;
    const unsigned P  = (unsigned)N + 1u;
    const unsigned P2 = P * P;
    const unsigned planeb = (unsigned)(b * 8) * P2;

    if (bx == 0) {
        // graph-token row (row 0) for all 8 heads
        #pragma unroll
        for (int h = 0; h < 8; h++) {
            const float tv = token[h];
            for (unsigned c = tid; c < P; c += TPB)
                out[planeb + (unsigned)h * P2 + c] = tv;
        }
        return;
    }

    const int r0 = 2 * (bx - 1) + 1;     // rows r0, r0+1 (interior)

    // graph-token column (col 0), both rows, all heads
    if (tid < 16) {
        const int h = tid & 7, dr = tid >> 3;
        out[planeb + (unsigned)h * P2 + (unsigned)(r0 + dr) * P] = token[h];
    }

    const int* __restrict__ srow0 =
        spatial + ((size_t)b * (size_t)N + (size_t)(r0 - 1)) * (size_t)N;
    const int* __restrict__ srow1 = srow0 + N;
    float* __restrict__ o0 = out + planeb + (unsigned)r0 * P + 1;
    float* __restrict__ o1 = o0 + P;

    const float4* __restrict__ tab = emb4s + CPY * (tid & 3);

    // Front-batch 8 independent global loads (4 column slots x 2 rows).
    int s0[4], s1[4];
    #pragma unroll
    for (int k = 0; k < 4; k++) {
        s0[k] = __ldg(srow0 + tid + k * TPB);
        s1[k] = __ldg(srow1 + tid + k * TPB);
    }

    #pragma unroll
    for (int k = 0; k < 4; k++) {
        const int c = tid + k * TPB;
        {
            const float4 va = tab[2 * s0[k]];
            const float4 vb = tab[2 * s0[k] + 1];
            float* __restrict__ p = o0 + c;
            p[0u * P2] = va.x;  p[1u * P2] = va.y;
            p[2u * P2] = va.z;  p[3u * P2] = va.w;
            p[4u * P2] = vb.x;  p[5u * P2] = vb.y;
            p[6u * P2] = vb.z;  p[7u * P2] = vb.w;
        }
        {
            const float4 va = tab[2 * s1[k]];
            const float4 vb = tab[2 * s1[k] + 1];
            float* __restrict__ p = o1 + c;
            p[0u * P2] = va.x;  p[1u * P2] = va.y;
            p[2u * P2] = va.z;  p[3u * P2] = va.w;
            p[4u * P2] = vb.x;  p[5u * P2] = vb.y;
            p[6u * P2] = vb.z;  p[7u * P2] = vb.w;
        }
    }
}

// Generic fallback (H != 8, table too big, or N not a multiple of 2*TPB).
#define G_ROWS 4
#define G_TPB 256

__global__ __launch_bounds__(G_TPB) void wbe_generic(
    const int*   __restrict__ spatial,
    const float* __restrict__ emb,
    const float* __restrict__ token,
    float*       __restrict__ out,
    int N, int H, int SP1)
{
    __shared__ float emb_s[4096];
    const int tid = threadIdx.x;
    int total = SP1 * H;
    if (total > 4096) total = 4096;
    for (int idx = tid; idx < total; idx += G_TPB) {
        int h = idx / SP1;
        int s = idx - h * SP1;
        emb_s[idx] = emb[s * H + h];
    }
    __syncthreads();

    const unsigned bh = blockIdx.y;
    const int h = (int)(bh % (unsigned)H);
    const int b = (int)(bh / (unsigned)H);
    const float tokv = token[h];
    const unsigned P  = (unsigned)N + 1u;
    const unsigned P2 = P * P;
    const float* __restrict__ eh = emb_s + h * SP1;
    float* __restrict__ plane = out + (size_t)bh * (size_t)P2;

    #pragma unroll
    for (int rr = 0; rr < G_ROWS; rr++) {
        const unsigned r = blockIdx.x * G_ROWS + rr;
        if (r >= P) return;
        float* __restrict__ orow = plane + (size_t)r * P;
        if (r == 0) {
            for (unsigned c = tid; c < P; c += G_TPB) orow[c] = tokv;
        } else {
            if (tid == 0) orow[0] = tokv;
            const int* __restrict__ srow =
                spatial + ((size_t)b * (size_t)N + (size_t)(r - 1)) * (size_t)N;
            for (unsigned c = tid; c < (unsigned)N; c += G_TPB)
                orow[1 + c] = eh[srow[c]];
        }
    }
}

extern "C" void kernel_launch(void* const* d_in, const int* in_sizes, int n_in,
                              void* d_out, int out_size)
{
    const int*   spatial = (const int*)  d_in[0];
    const float* emb     = (const float*)d_in[n_in - 2];
    const float* token   = (const float*)d_in[n_in - 1];

    const int E         = in_sizes[0];          // B*N*N
    const int num_nodes = in_sizes[2];          // B*N
    const int H         = in_sizes[n_in - 1];
    const int SP1       = in_sizes[n_in - 2] / H;
    const int N         = E / num_nodes;
    const int B         = num_nodes / N;
    const int P         = N + 1;

    if (H == 8 && SP1 * 2 <= CPY && (N % (2 * TPB)) == 0) {
        dim3 grid((unsigned)(1 + N / 2), (unsigned)B);
        wbe_fast8<<<grid, TPB>>>(spatial, emb, token, (float*)d_out, N, SP1);
    } else {
        dim3 grid((P + G_ROWS - 1) / G_ROWS, (unsigned)(B * H));
        wbe_generic<<<grid, G_TPB>>>(spatial, emb, token, (float*)d_out, N, H, SP1);
    }
}